// round 8
// baseline (speedup 1.0000x reference)
#include <cuda_runtime.h>
#include <cuda_bf16.h>
#include <cstdint>

// Problem constants
#define B_  8
#define T_  1024
#define C_  768
#define H_  12
#define HS_ 64
#define M_  8192   // B*T

// ---------------------------------------------------------------------------
// Device-global scratch (no runtime allocation allowed)
// ---------------------------------------------------------------------------
__device__ __nv_bfloat16 g_XH[(size_t)M_*C_], g_XL[(size_t)M_*C_];
__device__ __nv_bfloat16 g_YH[(size_t)M_*C_], g_YL[(size_t)M_*C_];
__device__ __nv_bfloat16 g_WaH[(size_t)3*C_*C_], g_WaL[(size_t)3*C_*C_];
__device__ __nv_bfloat16 g_WpH[(size_t)C_*C_],   g_WpL[(size_t)C_*C_];

// Q/K: [B,H,T,hs] bf16 hi/lo (Q prescaled by 0.125). V: TRANSPOSED [B,H,hs,T].
__device__ __nv_bfloat16 g_Qh[B_*H_*T_*HS_], g_Ql[B_*H_*T_*HS_];
__device__ __nv_bfloat16 g_Kh[B_*H_*T_*HS_], g_Kl[B_*H_*T_*HS_];
__device__ __nv_bfloat16 g_Vh[B_*H_*T_*HS_], g_Vl[B_*H_*T_*HS_];

// ---------------------------------------------------------------------------
// Helpers (portable PTX only — compiles for plain sm_103 target)
// ---------------------------------------------------------------------------
__device__ __forceinline__ uint32_t smem_u32(const void* p){
    return (uint32_t)__cvta_generic_to_shared(p);
}
__device__ __forceinline__ void cpa16(uint32_t d, const void* s){
    asm volatile("cp.async.cg.shared.global [%0], [%1], 16;" :: "r"(d), "l"(s));
}
__device__ __forceinline__ void ldsm4(uint32_t& r0, uint32_t& r1,
                                      uint32_t& r2, uint32_t& r3, uint32_t a){
    asm volatile("ldmatrix.sync.aligned.m8n8.x4.shared.b16 {%0,%1,%2,%3}, [%4];"
                 : "=r"(r0), "=r"(r1), "=r"(r2), "=r"(r3) : "r"(a));
}
__device__ __forceinline__ void mma16816(float acc[4], const uint32_t a[4],
                                         const uint32_t b[2]){
    asm volatile(
        "mma.sync.aligned.m16n8k16.row.col.f32.bf16.bf16.f32 "
        "{%0,%1,%2,%3}, {%4,%5,%6,%7}, {%8,%9}, {%0,%1,%2,%3};"
        : "+f"(acc[0]), "+f"(acc[1]), "+f"(acc[2]), "+f"(acc[3])
        : "r"(a[0]), "r"(a[1]), "r"(a[2]), "r"(a[3]), "r"(b[0]), "r"(b[1]));
}
__device__ __forceinline__ uint32_t packbf(float x, float y){
    __nv_bfloat162 t = __float22bfloat162_rn(make_float2(x, y));
    return *(uint32_t*)&t;
}
__device__ __forceinline__ float bfhi(float x){
    return __bfloat162float(__float2bfloat16(x));
}

// per-lane ldmatrix row-offset helpers (byte offsets within a tile):
__device__ __forceinline__ uint32_t lm_offA(int lane, int rowb){
    return (uint32_t)(((lane & 7) + ((lane >> 3) & 1)*8) * rowb + (lane >> 4)*16);
}
__device__ __forceinline__ uint32_t lm_offB(int lane, int rowb){
    return (uint32_t)(((lane & 7) + (lane >> 4)*8) * rowb + ((lane >> 3) & 1)*16);
}

// ---------------------------------------------------------------------------
// Pre-pass: split x fp32 -> bf16 hi/lo
// ---------------------------------------------------------------------------
__global__ void convert_split_x(const float* __restrict__ src)
{
    const int i = blockIdx.x * blockDim.x + threadIdx.x;   // float4 index
    const int n4 = (M_*C_) / 4;
    if (i >= n4) return;
    const float4 v = ((const float4*)src)[i];
    const float h0 = bfhi(v.x), h1 = bfhi(v.y), h2 = bfhi(v.z), h3 = bfhi(v.w);
    ((uint32_t*)g_XH)[i*2    ] = packbf(v.x, v.y);
    ((uint32_t*)g_XH)[i*2 + 1] = packbf(v.z, v.w);
    ((uint32_t*)g_XL)[i*2    ] = packbf(v.x - h0, v.y - h1);
    ((uint32_t*)g_XL)[i*2 + 1] = packbf(v.z - h2, v.w - h3);
}

// ---------------------------------------------------------------------------
// Pre-pass: transpose + split weights -> [N][768] bf16 hi/lo (K-major)
// ---------------------------------------------------------------------------
template<int WHICH>
__global__ void transpose_split(const float* __restrict__ w)
{
    constexpr int N = (WHICH == 0) ? 3*C_ : C_;
    __nv_bfloat16* Hh = (WHICH == 0) ? g_WaH : g_WpH;
    __nv_bfloat16* Ll = (WHICH == 0) ? g_WaL : g_WpL;

    __shared__ float tile[32][33];
    const int nb = blockIdx.x * 32;
    const int kb = blockIdx.y * 32;
    const int tx = threadIdx.x;
    const int ty = threadIdx.y;

    #pragma unroll
    for (int i = ty; i < 32; i += 8)
        tile[i][tx] = w[(size_t)(kb + i) * N + nb + tx];
    __syncthreads();

    #pragma unroll
    for (int i = ty; i < 32; i += 8){
        const float v = tile[tx][i];
        const __nv_bfloat16 h = __float2bfloat16(v);
        const __nv_bfloat16 l = __float2bfloat16(v - __bfloat162float(h));
        const size_t o = (size_t)(nb + i) * C_ + kb + tx;
        Hh[o] = h;
        Ll[o] = l;
    }
}

// ---------------------------------------------------------------------------
// Tensor-core GEMM (bf16 hi/lo, 3-pass compensation), ldmatrix loads,
// pass-major MMA order (4-way accumulator ILP).
// ---------------------------------------------------------------------------
constexpr int ROWB   = 80;
constexpr int MATB   = 128 * ROWB;
constexpr int STAGEB = 4 * MATB;
constexpr int GEMM_SMEM = 2 * STAGEB;   // 81920 B

template<int MODE>
__global__ __launch_bounds__(256, 2)
void mma_gemm(const float* __restrict__ bias, float* __restrict__ Cout)
{
    extern __shared__ __align__(128) uint8_t smem[];

    const __nv_bfloat16* AH = (MODE == 1) ? g_XH : g_YH;
    const __nv_bfloat16* AL = (MODE == 1) ? g_XL : g_YL;
    const __nv_bfloat16* BH = (MODE == 1) ? g_WaH : g_WpH;
    const __nv_bfloat16* BL = (MODE == 1) ? g_WaL : g_WpL;

    const int tid  = threadIdx.x;
    const int lane = tid & 31;
    const int warp = tid >> 5;
    const int wm   = warp & 1;
    const int wn   = warp >> 1;
    const int bc   = blockIdx.x;
    const int br   = blockIdx.y;

    const uint32_t sb = smem_u32(smem);

    auto load_stage = [&](int kt, int s){
        const uint32_t st = sb + (uint32_t)s * STAGEB;
        #pragma unroll
        for (int j = 0; j < 2; j++){
            const int ch  = tid + j*256;
            const int row = ch >> 2;
            const int cc  = ch & 3;
            const uint32_t so = (uint32_t)(row*ROWB + cc*16);
            const size_t ga = (size_t)(br*128 + row) * C_ + kt*32 + cc*8;
            const size_t gb = (size_t)(bc*128 + row) * C_ + kt*32 + cc*8;
            cpa16(st            + so, AH + ga);
            cpa16(st +   MATB   + so, AL + ga);
            cpa16(st + 2*MATB   + so, BH + gb);
            cpa16(st + 3*MATB   + so, BL + gb);
        }
        asm volatile("cp.async.commit_group;");
    };

    float acc[4][4][4];
    #pragma unroll
    for (int i = 0; i < 4; i++)
        #pragma unroll
        for (int j = 0; j < 4; j++)
            #pragma unroll
            for (int q = 0; q < 4; q++) acc[i][j][q] = 0.f;

    constexpr int NK = C_ / 32;    // 24

    load_stage(0, 0);
    asm volatile("cp.async.wait_group 0;");
    __syncthreads();

    const uint32_t offA = lm_offA(lane, ROWB) + (uint32_t)(wm*64)*ROWB;
    const uint32_t offB = lm_offB(lane, ROWB) + (uint32_t)(wn*32)*ROWB + 2*MATB;

    for (int kt = 0; kt < NK; kt++){
        const int cur = kt & 1;
        if (kt + 1 < NK) load_stage(kt + 1, cur ^ 1);

        const uint32_t st = sb + (uint32_t)cur * STAGEB;

        #pragma unroll
        for (int kk = 0; kk < 2; kk++){
            uint32_t bh[4][2], bl[4][2];
            #pragma unroll
            for (int jp = 0; jp < 2; jp++){
                const uint32_t ab = st + offB + (uint32_t)(jp*16)*ROWB + kk*32;
                ldsm4(bh[2*jp][0], bh[2*jp][1], bh[2*jp+1][0], bh[2*jp+1][1], ab);
                ldsm4(bl[2*jp][0], bl[2*jp][1], bl[2*jp+1][0], bl[2*jp+1][1],
                      ab + MATB);
            }
            #pragma unroll
            for (int i = 0; i < 4; i++){
                const uint32_t aa = st + offA + (uint32_t)(i*16)*ROWB + kk*32;
                uint32_t ah[4], al[4];
                ldsm4(ah[0], ah[1], ah[2], ah[3], aa);
                ldsm4(al[0], al[1], al[2], al[3], aa + MATB);
                // pass-major: consecutive MMAs hit 4 different accumulators
                #pragma unroll
                for (int j = 0; j < 4; j++) mma16816(acc[i][j], ah, bh[j]);
                #pragma unroll
                for (int j = 0; j < 4; j++) mma16816(acc[i][j], ah, bl[j]);
                #pragma unroll
                for (int j = 0; j < 4; j++) mma16816(acc[i][j], al, bh[j]);
            }
        }

        if (kt + 1 < NK) asm volatile("cp.async.wait_group 0;");
        __syncthreads();
    }

    const int r  = lane >> 2;
    const int c4 = lane & 3;

    // Epilogue
    #pragma unroll
    for (int j = 0; j < 4; j++){
        const int col = bc*128 + wn*32 + j*8 + c4*2;
        const float2 bv = *(const float2*)&bias[col];
        if (MODE == 0){
            #pragma unroll
            for (int i = 0; i < 4; i++){
                const int row0 = br*128 + wm*64 + i*16 + r;
                float2 v0 = make_float2(acc[i][j][0] + bv.x, acc[i][j][1] + bv.y);
                float2 v1 = make_float2(acc[i][j][2] + bv.x, acc[i][j][3] + bv.y);
                *(float2*)&Cout[(size_t)row0     * C_ + col] = v0;
                *(float2*)&Cout[(size_t)(row0+8) * C_ + col] = v1;
            }
        } else {
            const int which = col / C_;
            const int rem   = col - which * C_;
            const int hh = rem >> 6;
            const int dd = rem & 63;
            #pragma unroll
            for (int i = 0; i < 4; i++){
                const int row0 = br*128 + wm*64 + i*16 + r;
                const int b0i = row0 >> 10, t0i = row0 & 1023;
                const int row1 = row0 + 8;
                const int b1i = row1 >> 10, t1i = row1 & 1023;
                float v00 = acc[i][j][0] + bv.x, v01 = acc[i][j][1] + bv.y;
                float v10 = acc[i][j][2] + bv.x, v11 = acc[i][j][3] + bv.y;
                if (which == 0){ v00*=0.125f; v01*=0.125f; v10*=0.125f; v11*=0.125f; }
                if (which < 2){
                    __nv_bfloat16* DH = (which == 0) ? g_Qh : g_Kh;
                    __nv_bfloat16* DL = (which == 0) ? g_Ql : g_Kl;
                    const size_t o0 = ((size_t)(b0i*H_ + hh)*T_ + t0i)*HS_ + dd;
                    const size_t o1 = ((size_t)(b1i*H_ + hh)*T_ + t1i)*HS_ + dd;
                    *(uint32_t*)&DH[o0] = packbf(v00, v01);
                    *(uint32_t*)&DL[o0] = packbf(v00 - bfhi(v00), v01 - bfhi(v01));
                    *(uint32_t*)&DH[o1] = packbf(v10, v11);
                    *(uint32_t*)&DL[o1] = packbf(v10 - bfhi(v10), v11 - bfhi(v11));
                } else {
                    const size_t vb0 = ((size_t)(b0i*H_ + hh)*HS_ + dd)*T_;
                    const size_t vb1 = ((size_t)(b1i*H_ + hh)*HS_ + dd)*T_;
                    g_Vh[vb0      + t0i] = __float2bfloat16(v00);
                    g_Vh[vb0 + T_ + t0i] = __float2bfloat16(v01);
                    g_Vh[vb1      + t1i] = __float2bfloat16(v10);
                    g_Vh[vb1 + T_ + t1i] = __float2bfloat16(v11);
                    g_Vl[vb0      + t0i] = __float2bfloat16(v00 - bfhi(v00));
                    g_Vl[vb0 + T_ + t0i] = __float2bfloat16(v01 - bfhi(v01));
                    g_Vl[vb1      + t1i] = __float2bfloat16(v10 - bfhi(v10));
                    g_Vl[vb1 + T_ + t1i] = __float2bfloat16(v11 - bfhi(v11));
                }
            }
        }
    }
}

// ---------------------------------------------------------------------------
// Tensor-core causal flash attention; 32-row K/V blocks, pass-major MMA order
// (4 accumulators interleaved -> same-acc distance 4).
// ---------------------------------------------------------------------------
constexpr int AT_ROWK = 144;
constexpr int AT_ROWV = 272;
constexpr int AT_MK   = 128 * AT_ROWK;
constexpr int AT_MV   = 64  * AT_ROWV;
constexpr int AT_Q    = 2 * AT_MK;
constexpr int AT_STAGE= 2*AT_MK + 2*AT_MV;
constexpr int ATTN_SMEM = AT_Q + 2*AT_STAGE;   // 180224

__global__ __launch_bounds__(256, 1)
void attn_tc()
{
    extern __shared__ __align__(128) uint8_t smx[];
    const uint32_t sb = smem_u32(smx);

    const int qt  = blockIdx.x;
    const int bh  = blockIdx.y;
    const int tid = threadIdx.x;
    const int lane = tid & 31;
    const int w    = tid >> 5;
    const int r    = lane >> 2;
    const int c4   = lane & 3;

    const size_t qoff = ((size_t)bh*T_ + qt*128) * HS_;
    #pragma unroll
    for (int j = 0; j < 4; j++){
        const int ch = tid + 256*j;
        const int row = ch >> 3, c = ch & 7;
        const uint32_t so = sb + (uint32_t)(row*AT_ROWK + c*16);
        const size_t g = qoff + (size_t)row*HS_ + c*8;
        cpa16(so,         g_Qh + g);
        cpa16(so + AT_MK, g_Ql + g);
    }

    auto load_kv = [&](int kt, int s){
        const uint32_t st = sb + AT_Q + (uint32_t)s * AT_STAGE;
        const size_t koff = ((size_t)bh*T_ + kt*128) * HS_;
        #pragma unroll
        for (int j = 0; j < 4; j++){
            const int ch = tid + 256*j;
            const int row = ch >> 3, c = ch & 7;
            const uint32_t so = st + (uint32_t)(row*AT_ROWK + c*16);
            const size_t g = koff + (size_t)row*HS_ + c*8;
            cpa16(so,         g_Kh + g);
            cpa16(so + AT_MK, g_Kl + g);
        }
        const size_t voff = (size_t)bh*HS_*T_ + kt*128;
        #pragma unroll
        for (int j = 0; j < 4; j++){
            const int ch = tid + 256*j;
            const int row = ch >> 4, c = ch & 15;
            const uint32_t so = st + 2*AT_MK + (uint32_t)(row*AT_ROWV + c*16);
            const size_t g = voff + (size_t)row*T_ + c*8;
            cpa16(so,         g_Vh + g);
            cpa16(so + AT_MV, g_Vl + g);
        }
        asm volatile("cp.async.commit_group;");
    };

    load_kv(0, 0);

    float m0 = -1e30f, m1 = -1e30f, l0 = 0.f, l1 = 0.f;
    float o[8][4];
    #pragma unroll
    for (int j2 = 0; j2 < 8; j2++)
        #pragma unroll
        for (int q = 0; q < 4; q++) o[j2][q] = 0.f;

    const uint32_t offQ = lm_offA(lane, AT_ROWK) + (uint32_t)(w*16)*AT_ROWK;
    const uint32_t offK = lm_offB(lane, AT_ROWK);
    const uint32_t offV = lm_offB(lane, AT_ROWV);

    for (int kt = 0; kt <= qt; kt++){
        if (kt < qt){
            load_kv(kt + 1, (kt + 1) & 1);
            asm volatile("cp.async.wait_group 1;");
        } else {
            asm volatile("cp.async.wait_group 0;");
        }
        __syncthreads();

        const uint32_t st = sb + AT_Q + (uint32_t)(kt & 1) * AT_STAGE;

        // ---- S = Q @ K^T (3-pass hi/lo), 32-row K blocks, pass-major ----
        float s[16][4];
        #pragma unroll
        for (int j = 0; j < 16; j++){
            s[j][0] = s[j][1] = s[j][2] = s[j][3] = 0.f;
        }
        #pragma unroll
        for (int kk = 0; kk < 4; kk++){
            uint32_t qh[4], ql[4];
            {
                const uint32_t qa = sb + offQ + kk*32;
                ldsm4(qh[0], qh[1], qh[2], qh[3], qa);
                ldsm4(ql[0], ql[1], ql[2], ql[3], qa + AT_MK);
            }
            #pragma unroll
            for (int jq = 0; jq < 4; jq++){        // 32 K-rows per block
                const uint32_t ka = st + offK + (uint32_t)(jq*32)*AT_ROWK + kk*32;
                uint32_t kh[4][2], kl[4][2];
                ldsm4(kh[0][0], kh[0][1], kh[1][0], kh[1][1], ka);
                ldsm4(kh[2][0], kh[2][1], kh[3][0], kh[3][1],
                      ka + (uint32_t)16*AT_ROWK);
                ldsm4(kl[0][0], kl[0][1], kl[1][0], kl[1][1], ka + AT_MK);
                ldsm4(kl[2][0], kl[2][1], kl[3][0], kl[3][1],
                      ka + AT_MK + (uint32_t)16*AT_ROWK);
                float* s0 = s[4*jq + 0]; float* s1 = s[4*jq + 1];
                float* s2 = s[4*jq + 2]; float* s3 = s[4*jq + 3];
                mma16816(s0, qh, kh[0]); mma16816(s1, qh, kh[1]);
                mma16816(s2, qh, kh[2]); mma16816(s3, qh, kh[3]);
                mma16816(s0, qh, kl[0]); mma16816(s1, qh, kl[1]);
                mma16816(s2, qh, kl[2]); mma16816(s3, qh, kl[3]);
                mma16816(s0, ql, kh[0]); mma16816(s1, ql, kh[1]);
                mma16816(s2, ql, kh[2]); mma16816(s3, ql, kh[3]);
            }
        }

        // ---- causal mask on diagonal tile ----
        if (kt == qt){
            const int row0 = w*16 + r;
            #pragma unroll
            for (int j = 0; j < 16; j++){
                const int col0 = j*8 + c4*2;
                if (col0     > row0    ) s[j][0] = -1e30f;
                if (col0 + 1 > row0    ) s[j][1] = -1e30f;
                if (col0     > row0 + 8) s[j][2] = -1e30f;
                if (col0 + 1 > row0 + 8) s[j][3] = -1e30f;
            }
        }

        // ---- online softmax ----
        float rm0 = -1e30f, rm1 = -1e30f;
        #pragma unroll
        for (int j = 0; j < 16; j++){
            rm0 = fmaxf(rm0, fmaxf(s[j][0], s[j][1]));
            rm1 = fmaxf(rm1, fmaxf(s[j][2], s[j][3]));
        }
        rm0 = fmaxf(rm0, __shfl_xor_sync(0xffffffffu, rm0, 1));
        rm0 = fmaxf(rm0, __shfl_xor_sync(0xffffffffu, rm0, 2));
        rm1 = fmaxf(rm1, __shfl_xor_sync(0xffffffffu, rm1, 1));
        rm1 = fmaxf(rm1, __shfl_xor_sync(0xffffffffu, rm1, 2));
        const float mn0 = fmaxf(m0, rm0), mn1 = fmaxf(m1, rm1);
        const float a0 = __expf(m0 - mn0), a1 = __expf(m1 - mn1);
        m0 = mn0; m1 = mn1;
        float rs0 = 0.f, rs1 = 0.f;
        #pragma unroll
        for (int j = 0; j < 16; j++){
            s[j][0] = __expf(s[j][0] - mn0);
            s[j][1] = __expf(s[j][1] - mn0);
            s[j][2] = __expf(s[j][2] - mn1);
            s[j][3] = __expf(s[j][3] - mn1);
            rs0 += s[j][0] + s[j][1];
            rs1 += s[j][2] + s[j][3];
        }
        rs0 += __shfl_xor_sync(0xffffffffu, rs0, 1);
        rs0 += __shfl_xor_sync(0xffffffffu, rs0, 2);
        rs1 += __shfl_xor_sync(0xffffffffu, rs1, 1);
        rs1 += __shfl_xor_sync(0xffffffffu, rs1, 2);
        l0 = l0*a0 + rs0;
        l1 = l1*a1 + rs1;
        #pragma unroll
        for (int j2 = 0; j2 < 8; j2++){
            o[j2][0] *= a0; o[j2][1] *= a0;
            o[j2][2] *= a1; o[j2][3] *= a1;
        }

        // ---- O += P @ V (3-pass), 32-row V blocks, pass-major ----
        const uint32_t vbase = st + 2*AT_MK;
        #pragma unroll
        for (int kk = 0; kk < 8; kk++){
            float ph[8], pl[8];
            #pragma unroll
            for (int e = 0; e < 4; e++){
                ph[e]   = bfhi(s[2*kk  ][e]);  pl[e]   = s[2*kk  ][e] - ph[e];
                ph[4+e] = bfhi(s[2*kk+1][e]);  pl[4+e] = s[2*kk+1][e] - ph[4+e];
            }
            uint32_t a_h[4], a_l[4];
            a_h[0] = packbf(ph[0], ph[1]);  a_h[1] = packbf(ph[2], ph[3]);
            a_h[2] = packbf(ph[4], ph[5]);  a_h[3] = packbf(ph[6], ph[7]);
            a_l[0] = packbf(pl[0], pl[1]);  a_l[1] = packbf(pl[2], pl[3]);
            a_l[2] = packbf(pl[4], pl[5]);  a_l[3] = packbf(pl[6], pl[7]);
            #pragma unroll
            for (int jq = 0; jq < 2; jq++){        // 32 V-columns per block
                const uint32_t va = vbase + offV + (uint32_t)(jq*32)*AT_ROWV
                                  + kk*32;
                uint32_t vh[4][2], vl[4][2];
                ldsm4(vh[0][0], vh[0][1], vh[1][0], vh[1][1], va);
                ldsm4(vh[2][0], vh[2][1], vh[3][0], vh[3][1],
                      va + (uint32_t)16*AT_ROWV);
                ldsm4(vl[0][0], vl[0][1], vl[1][0], vl[1][1], va + AT_MV);
                ldsm4(vl[2][0], vl[2][1], vl[3][0], vl[3][1],
                      va + AT_MV + (uint32_t)16*AT_ROWV);
                float* o0 = o[4*jq + 0]; float* o1 = o[4*jq + 1];
                float* o2 = o[4*jq + 2]; float* o3 = o[4*jq + 3];
                mma16816(o0, a_h, vh[0]); mma16816(o1, a_h, vh[1]);
                mma16816(o2, a_h, vh[2]); mma16816(o3, a_h, vh[3]);
                mma16816(o0, a_h, vl[0]); mma16816(o1, a_h, vl[1]);
                mma16816(o2, a_h, vl[2]); mma16816(o3, a_h, vl[3]);
                mma16816(o0, a_l, vh[0]); mma16816(o1, a_l, vh[1]);
                mma16816(o2, a_l, vh[2]); mma16816(o3, a_l, vh[3]);
            }
        }
        __syncthreads();
    }

    // ---- epilogue: write YH/YL bf16 hi/lo [M][768] ----
    const float inv0 = 1.f / l0, inv1 = 1.f / l1;
    const int bq = bh / H_, hh = bh % H_;
    const int t0 = qt*128 + w*16 + r;
    #pragma unroll
    for (int j2 = 0; j2 < 8; j2++){
        const int cc = hh*64 + j2*8 + c4*2;
        const float y0 = o[j2][0]*inv0, y1 = o[j2][1]*inv0;
        const float y2 = o[j2][2]*inv1, y3 = o[j2][3]*inv1;
        const size_t r0 = (size_t)(bq*T_ + t0    )*C_ + cc;
        const size_t r1 = (size_t)(bq*T_ + t0 + 8)*C_ + cc;
        *(uint32_t*)&g_YH[r0] = packbf(y0, y1);
        *(uint32_t*)&g_YL[r0] = packbf(y0 - bfhi(y0), y1 - bfhi(y1));
        *(uint32_t*)&g_YH[r1] = packbf(y2, y3);
        *(uint32_t*)&g_YL[r1] = packbf(y2 - bfhi(y2), y3 - bfhi(y3));
    }
}

// ---------------------------------------------------------------------------
extern "C" void kernel_launch(void* const* d_in, const int* in_sizes, int n_in,
                              void* d_out, int out_size)
{
    const float* x      = (const float*)d_in[0];
    const float* w_attn = (const float*)d_in[1];
    const float* b_attn = (const float*)d_in[2];
    const float* w_proj = (const float*)d_in[3];
    const float* b_proj = (const float*)d_in[4];
    float* out = (float*)d_out;

    cudaFuncSetAttribute(mma_gemm<1>, cudaFuncAttributeMaxDynamicSharedMemorySize, GEMM_SMEM);
    cudaFuncSetAttribute(mma_gemm<0>, cudaFuncAttributeMaxDynamicSharedMemorySize, GEMM_SMEM);
    cudaFuncSetAttribute(attn_tc, cudaFuncAttributeMaxDynamicSharedMemorySize, ATTN_SMEM);

    convert_split_x<<<(M_*C_/4 + 255)/256, 256>>>(x);
    transpose_split<0><<<dim3(3*C_/32, C_/32), dim3(32, 8)>>>(w_attn);
    transpose_split<1><<<dim3(C_/32,   C_/32), dim3(32, 8)>>>(w_proj);

    mma_gemm<1><<<dim3(3*C_/128, M_/128), 256, GEMM_SMEM>>>(b_attn, nullptr);
    attn_tc<<<dim3(T_/128, B_*H_), 256, ATTN_SMEM>>>();
    mma_gemm<0><<<dim3(C_/128, M_/128), 256, GEMM_SMEM>>>(b_proj, out);
}